// round 1
// baseline (speedup 1.0000x reference)
#include <cuda_runtime.h>
#include <cstdint>

#define N0      4096
#define NUM     8192
#define DD      512
#define CLASSES 100

// ---- device scratch (allowed: __device__ globals, no runtime alloc) ----
__device__ float g_x2[(size_t)NUM * DD];       // concat(x, x_ul)   16 MB
__device__ float g_bb[NUM];                    // squared norms
__device__ float g_y2[NUM];                    // concat(y, y_ul)
__device__ float g_S[(size_t)NUM * NUM];       // score matrix     256 MB
__device__ float g_musum[CLASSES * DD];
__device__ float g_cnt[CLASSES];
__device__ float g_mu[CLASSES * DD];
__device__ float g_mumu[CLASSES];
__device__ float g_ptgm[NUM];
__device__ float g_ptknn[NUM];

// ---------------------------------------------------------------
// build x2 = [x ; lam*x + (1-lam)*x[perm]], norms, y2 lower half
// grid NUM, block 128
// ---------------------------------------------------------------
__global__ void build_kernel(const float* __restrict__ x, const float* __restrict__ y,
                             const float* __restrict__ lamp, const int* __restrict__ perm) {
    int row = blockIdx.x;
    int tid = threadIdx.x;
    float ss = 0.f;
    float4* dst = (float4*)(g_x2 + (size_t)row * DD);
    if (row < N0) {
        const float4* src = (const float4*)(x + (size_t)row * DD);
        float4 v = src[tid];
        dst[tid] = v;
        ss = v.x * v.x + v.y * v.y + v.z * v.z + v.w * v.w;
        if (tid == 0) g_y2[row] = y[row];
    } else {
        int j = row - N0;
        float lam = *lamp;
        float oml = 1.f - lam;
        int p = perm[j];
        const float4* a = (const float4*)(x + (size_t)j * DD);
        const float4* b = (const float4*)(x + (size_t)p * DD);
        float4 va = a[tid], vb = b[tid], v;
        v.x = va.x * lam + vb.x * oml;
        v.y = va.y * lam + vb.y * oml;
        v.z = va.z * lam + vb.z * oml;
        v.w = va.w * lam + vb.w * oml;
        dst[tid] = v;
        ss = v.x * v.x + v.y * v.y + v.z * v.z + v.w * v.w;
    }
    __shared__ float red[128];
    red[tid] = ss;
    __syncthreads();
    #pragma unroll
    for (int s = 64; s > 0; s >>= 1) {
        if (tid < s) red[tid] += red[tid + s];
        __syncthreads();
    }
    if (tid == 0) g_bb[row] = red[0];
}

// ---------------------------------------------------------------
// score GEMM:  S[i][j] = bb[j] - 2 * dot(Q[i], B[j])
// Q = g_x2 + qoff*DD (M rows), B = g_x2 (N rows), K = DD = 512
// 128x128 tile, 256 threads, 8x8 micro-tile, BK=16, double buffered
// ---------------------------------------------------------------
__global__ __launch_bounds__(256, 2) void gemm_dist(int qoff, int M, int N) {
    __shared__ float As[2][16][128];
    __shared__ float Bs[2][16][128];
    int tid = threadIdx.x;
    int tx = tid & 15, ty = tid >> 4;
    const float* Qb = g_x2 + (size_t)(qoff + blockIdx.y * 128) * DD;
    const float* Bb = g_x2 + (size_t)(blockIdx.x * 128) * DD;

    float acc[8][8];
    #pragma unroll
    for (int u = 0; u < 8; u++)
        #pragma unroll
        for (int v = 0; v < 8; v++) acc[u][v] = 0.f;

    int lrow = tid >> 2;          // 0..63
    int lk   = (tid & 3) * 4;     // 0,4,8,12

    // preload chunk 0
    #pragma unroll
    for (int l = 0; l < 2; l++) {
        int row = lrow + l * 64;
        float4 va = *(const float4*)(Qb + (size_t)row * DD + lk);
        As[0][lk + 0][row] = va.x; As[0][lk + 1][row] = va.y;
        As[0][lk + 2][row] = va.z; As[0][lk + 3][row] = va.w;
        float4 vb = *(const float4*)(Bb + (size_t)row * DD + lk);
        Bs[0][lk + 0][row] = vb.x; Bs[0][lk + 1][row] = vb.y;
        Bs[0][lk + 2][row] = vb.z; Bs[0][lk + 3][row] = vb.w;
    }
    __syncthreads();

    int buf = 0;
    for (int k0 = 16; k0 <= DD; k0 += 16) {
        if (k0 < DD) {
            int nb = buf ^ 1;
            #pragma unroll
            for (int l = 0; l < 2; l++) {
                int row = lrow + l * 64;
                float4 va = *(const float4*)(Qb + (size_t)row * DD + k0 + lk);
                As[nb][lk + 0][row] = va.x; As[nb][lk + 1][row] = va.y;
                As[nb][lk + 2][row] = va.z; As[nb][lk + 3][row] = va.w;
                float4 vb = *(const float4*)(Bb + (size_t)row * DD + k0 + lk);
                Bs[nb][lk + 0][row] = vb.x; Bs[nb][lk + 1][row] = vb.y;
                Bs[nb][lk + 2][row] = vb.z; Bs[nb][lk + 3][row] = vb.w;
            }
        }
        #pragma unroll
        for (int kk = 0; kk < 16; kk++) {
            float a[8], b[8];
            *(float4*)&a[0] = *(const float4*)&As[buf][kk][ty * 8];
            *(float4*)&a[4] = *(const float4*)&As[buf][kk][ty * 8 + 4];
            *(float4*)&b[0] = *(const float4*)&Bs[buf][kk][tx * 8];
            *(float4*)&b[4] = *(const float4*)&Bs[buf][kk][tx * 8 + 4];
            #pragma unroll
            for (int u = 0; u < 8; u++)
                #pragma unroll
                for (int v = 0; v < 8; v++)
                    acc[u][v] = fmaf(a[u], b[v], acc[u][v]);
        }
        __syncthreads();
        buf ^= 1;
    }

    int colbase = blockIdx.x * 128 + tx * 8;
    float bbr[8];
    *(float4*)&bbr[0] = *(const float4*)&g_bb[colbase];
    *(float4*)&bbr[4] = *(const float4*)&g_bb[colbase + 4];
    #pragma unroll
    for (int u = 0; u < 8; u++) {
        size_t ro = (size_t)(blockIdx.y * 128 + ty * 8 + u) * N + colbase;
        float4 o0, o1;
        o0.x = bbr[0] - 2.f * acc[u][0];
        o0.y = bbr[1] - 2.f * acc[u][1];
        o0.z = bbr[2] - 2.f * acc[u][2];
        o0.w = bbr[3] - 2.f * acc[u][3];
        o1.x = bbr[4] - 2.f * acc[u][4];
        o1.y = bbr[5] - 2.f * acc[u][5];
        o1.z = bbr[6] - 2.f * acc[u][6];
        o1.w = bbr[7] - 2.f * acc[u][7];
        *(float4*)&g_S[ro]     = o0;
        *(float4*)&g_S[ro + 4] = o1;
    }
}

// ---------------------------------------------------------------
// warp-cooperative top-K smallest (value, index) with jax tie-break
// (lower index wins on equal value). Results sorted ascending.
// ---------------------------------------------------------------
template <int K>
__device__ __forceinline__ void topk_warp(const float* __restrict__ Srow, int N, int lane,
                                          float* out_v, int* out_i) {
    float v[K]; int ix[K];
    #pragma unroll
    for (int t = 0; t < K; t++) { v[t] = INFINITY; ix[t] = 0x7fffffff; }
    for (int j = lane; j < N; j += 32) {
        float s = Srow[j];
        bool better = (s < v[K - 1]) || (s == v[K - 1] && j < ix[K - 1]);
        if (better) {
            v[K - 1] = s; ix[K - 1] = j;
            #pragma unroll
            for (int t = K - 1; t > 0; t--) {
                bool sw = (v[t] < v[t - 1]) || (v[t] == v[t - 1] && ix[t] < ix[t - 1]);
                float tv = sw ? v[t - 1] : v[t];
                float bv = sw ? v[t] : v[t - 1];
                int   ti = sw ? ix[t - 1] : ix[t];
                int   bi = sw ? ix[t] : ix[t - 1];
                v[t] = tv; v[t - 1] = bv; ix[t] = ti; ix[t - 1] = bi;
            }
        }
    }
    #pragma unroll
    for (int r = 0; r < K; r++) {
        float bv = v[0]; int bi = ix[0];
        #pragma unroll
        for (int o = 16; o > 0; o >>= 1) {
            float ov = __shfl_xor_sync(0xffffffffu, bv, o);
            int   oi = __shfl_xor_sync(0xffffffffu, bi, o);
            if (ov < bv || (ov == bv && oi < bi)) { bv = ov; bi = oi; }
        }
        out_v[r] = bv; out_i[r] = bi;
        if (bv == v[0] && bi == ix[0]) {   // unique owner pops
            #pragma unroll
            for (int t = 0; t < K - 1; t++) { v[t] = v[t + 1]; ix[t] = ix[t + 1]; }
            v[K - 1] = INFINITY; ix[K - 1] = 0x7fffffff;
        }
    }
}

// torch.mode semantics: most frequent, smallest value on tie
template <int K>
__device__ __forceinline__ float mode_k(const float* lab) {
    float best = 0.f; int bc = -1;
    #pragma unroll
    for (int a = 0; a < K; a++) {
        int c = 0;
        #pragma unroll
        for (int b = 0; b < K; b++) c += (lab[a] == lab[b]);
        if (c > bc || (c == bc && lab[a] < best)) { bc = c; best = lab[a]; }
    }
    return best;
}

// mixup: 11-NN of x_ul among x, mode label -> y2 upper half. warp/row.
__global__ void topk_mixup_kernel() {
    int warp = (blockIdx.x * blockDim.x + threadIdx.x) >> 5;
    int lane = threadIdx.x & 31;
    if (warp >= N0) return;
    const float* Srow = g_S + (size_t)warp * N0;
    float rv[11]; int ri[11];
    topk_warp<11>(Srow, N0, lane, rv, ri);
    if (lane == 0) {
        float lab[11];
        #pragma unroll
        for (int t = 0; t < 11; t++) lab[t] = g_y2[ri[t]];
        g_y2[N0 + warp] = mode_k<11>(lab);
    }
}

// knn reg: top-4 smallest (first is the minimal element, dropped like idxk[:,1:])
__global__ void topk_knn_kernel() {
    int warp = (blockIdx.x * blockDim.x + threadIdx.x) >> 5;
    int lane = threadIdx.x & 31;
    if (warp >= NUM) return;
    const float* Srow = g_S + (size_t)warp * NUM;
    float rv[4]; int ri[4];
    topk_warp<4>(Srow, NUM, lane, rv, ri);
    if (lane == 0) {
        float lab[3];
        lab[0] = g_y2[ri[1]]; lab[1] = g_y2[ri[2]]; lab[2] = g_y2[ri[3]];
        float m = mode_k<3>(lab);
        float d = m - g_y2[warp];
        g_ptknn[warp] = d * d;
    }
}

// ---------------------------------------------------------------
// class statistics
// ---------------------------------------------------------------
__global__ void zero_stats_kernel() {
    int i = blockIdx.x * blockDim.x + threadIdx.x;
    if (i < CLASSES * DD) g_musum[i] = 0.f;
    if (i < CLASSES)      g_cnt[i]   = 0.f;
}

__global__ void scatter_kernel() {   // grid NUM, block 128
    int i = blockIdx.x;
    int tid = threadIdx.x;
    int c = (int)g_y2[i];
    const float* xr = g_x2 + (size_t)i * DD;
    for (int d = tid; d < DD; d += 128)
        atomicAdd(&g_musum[c * DD + d], xr[d]);
    if (tid == 0) atomicAdd(&g_cnt[c], 1.f);
}

__global__ void mu_kernel() {        // grid CLASSES, block 128
    int c = blockIdx.x, tid = threadIdx.x;
    float inv = 1.f / fmaxf(g_cnt[c], 1.f);
    float ss = 0.f;
    for (int d = tid; d < DD; d += 128) {
        float m = g_musum[c * DD + d] * inv;
        g_mu[c * DD + d] = m;
        ss += m * m;
    }
    __shared__ float red[128];
    red[tid] = ss;
    __syncthreads();
    #pragma unroll
    for (int s = 64; s > 0; s >>= 1) {
        if (tid < s) red[tid] += red[tid + s];
        __syncthreads();
    }
    if (tid == 0) g_mumu[c] = red[0];
}

// gm loss per point: grid NUM, block 128 (thread c < 100 owns class c)
__global__ void gm_kernel() {
    int i = blockIdx.x, tid = threadIdx.x;
    __shared__ float xs[DD];
    for (int d = tid; d < DD; d += 128) xs[d] = g_x2[(size_t)i * DD + d];
    __syncthreads();

    float w = 0.f;
    int c = tid;
    if (c < CLASSES) {
        const float4* mu4 = (const float4*)(g_mu + c * DD);
        const float4* xs4 = (const float4*)xs;
        float dot = 0.f;
        #pragma unroll 4
        for (int k = 0; k < DD / 4; k++) {
            float4 a = xs4[k], b = mu4[k];
            dot = fmaf(a.x, b.x, dot);
            dot = fmaf(a.y, b.y, dot);
            dot = fmaf(a.z, b.z, dot);
            dot = fmaf(a.w, b.w, dot);
        }
        float d2 = g_bb[i] + g_mumu[c] - 2.f * dot;
        w = (g_cnt[c] > 0.f) ? expf(-0.5f * d2) : 0.f;
    }
    __shared__ float red[128];
    red[tid] = w;
    __syncthreads();
    #pragma unroll
    for (int s = 64; s > 0; s >>= 1) {
        if (tid < s) red[tid] += red[tid + s];
        __syncthreads();
    }
    float wsum = red[0];
    __syncthreads();

    float t = 0.f;
    if (c < CLASSES) {
        float p = w / (wsum + 1e-15f);
        p = fminf(fmaxf(p, 0.f), 1.f);
        int yi = (int)g_y2[i];
        float dd = p - ((c == yi) ? 1.f : 0.f);
        t = dd * dd;
    }
    red[tid] = t;
    __syncthreads();
    #pragma unroll
    for (int s = 64; s > 0; s >>= 1) {
        if (tid < s) red[tid] += red[tid + s];
        __syncthreads();
    }
    if (tid == 0) g_ptgm[i] = red[0];
}

__global__ void final_kernel(float* __restrict__ out) {
    __shared__ float red[256];
    int tid = threadIdx.x;
    float s1 = 0.f, s2 = 0.f;
    for (int i = tid; i < NUM; i += 256) { s1 += g_ptgm[i]; s2 += g_ptknn[i]; }
    red[tid] = s1;
    __syncthreads();
    #pragma unroll
    for (int s = 128; s > 0; s >>= 1) {
        if (tid < s) red[tid] += red[tid + s];
        __syncthreads();
    }
    float t1 = red[0];
    __syncthreads();
    red[tid] = s2;
    __syncthreads();
    #pragma unroll
    for (int s = 128; s > 0; s >>= 1) {
        if (tid < s) red[tid] += red[tid + s];
        __syncthreads();
    }
    if (tid == 0) out[0] = t1 / (float)NUM + 0.01f * red[0] / (float)NUM;
}

// ---------------------------------------------------------------
extern "C" void kernel_launch(void* const* d_in, const int* in_sizes, int n_in,
                              void* d_out, int out_size) {
    const float* x    = (const float*)d_in[0];
    const float* y    = (const float*)d_in[1];
    const float* lam  = (const float*)d_in[2];
    const int*   perm = (const int*)d_in[3];
    float* out = (float*)d_out;

    build_kernel<<<NUM, 128>>>(x, y, lam, perm);

    // mixup distances: queries x_ul (rows N0..), base x (rows 0..N0)
    dim3 g1(N0 / 128, N0 / 128);
    gemm_dist<<<g1, 256>>>(N0, N0, N0);
    topk_mixup_kernel<<<N0 / 8, 256>>>();

    // knn distances over concatenated set
    dim3 g2(NUM / 128, NUM / 128);
    gemm_dist<<<g2, 256>>>(0, NUM, NUM);
    topk_knn_kernel<<<NUM / 8, 256>>>();

    // class stats + gm loss
    zero_stats_kernel<<<(CLASSES * DD + 255) / 256, 256>>>();
    scatter_kernel<<<NUM, 128>>>();
    mu_kernel<<<CLASSES, 128>>>();
    gm_kernel<<<NUM, 128>>>();

    final_kernel<<<1, 256>>>(out);
}